// round 6
// baseline (speedup 1.0000x reference)
#include <cuda_runtime.h>
#include <cuda_bf16.h>
#include <math.h>

#define BB    2304
#define CH    22
#define TP    250
#define ST    64
#define KW    13
#define RR    32
#define NFE   528

typedef unsigned long long ull;

__device__ float g_z[(size_t)BB * ST * TP];
__device__ float g_y[(size_t)BB * RR * RR];

__device__ __forceinline__ ull pk2(float a, float b) {
    ull r;
    asm("mov.b64 %0, {%1, %2};" : "=l"(r)
        : "r"(__float_as_uint(a)), "r"(__float_as_uint(b)));
    return r;
}
__device__ __forceinline__ void upk2(ull v, float &a, float &b) {
    unsigned int lo, hi;
    asm("mov.b64 {%0, %1}, %2;" : "=r"(lo), "=r"(hi) : "l"(v));
    a = __uint_as_float(lo); b = __uint_as_float(hi);
}
__device__ __forceinline__ void fma2(ull &d, ull a, ull b) {
    asm("fma.rn.f32x2 %0, %1, %2, %0;" : "+l"(d) : "l"(a), "l"(b));
}

// ============================================================
// K1: pool(4) + conv(22x13,pad6) + BN -> g_z[b][o][t]
// grid (4, 2304): x = og (16 o), y = b  (og-blocks of same b adjacent
// in schedule -> x row re-reads hit L2).
// 256 threads: thread = (o = og*16 + tid>>4, chunk ln = tid&15 of 16 t).
// smem: region A (36.6KB: xpf then w2) + xs (76KB pre-paired windows)
//   -> 110KB total, 2 blocks/SM, 16 warps/SM.
// Inner loop: LDS.64 (conflict-free) + FFMA2 only.
// ============================================================
#define W2A_ULL   (16 * 286)               // 4576 ull = 36608 B (region A)
#define XS_ULL    (CH * 16 * 27)           // 9504 ull = 76032 B
#define CONV_SMEM ((W2A_ULL + XS_ULL) * 8) // 112640 B

__global__ void __launch_bounds__(256, 2)
k_conv(const float* __restrict__ x, const float* __restrict__ cw,
       const float* __restrict__ cb, const float* __restrict__ bg,
       const float* __restrict__ bbv, const float* __restrict__ bm,
       const float* __restrict__ bv)
{
    extern __shared__ ull dsm[];
    ull*   w2  = dsm;                   // region A as packed weights (phase 3+)
    float* xpf = (float*)dsm;           // region A as pooled input (phases 1-2)
    ull*   xs  = dsm + W2A_ULL;         // pre-paired windows
    __shared__ float sc[16], sh[16];

    int og = blockIdx.x, b = blockIdx.y, tid = threadIdx.x;

    // phase 1: zero-pad + pool(4) into xpf (22 x 272, pad 6 front)
    for (int i = tid; i < CH * 272; i += 256) xpf[i] = 0.f;
    __syncthreads();
    const float4* xb = (const float4*)(x + (size_t)b * CH * 1000);
    for (int i = tid; i < CH * TP; i += 256) {
        int c = i / TP, t = i - c * TP;
        float4 v = xb[i];
        xpf[c * 272 + 6 + t] = 0.25f * (v.x + v.y + v.z + v.w);
    }
    __syncthreads();

    // phase 2: pre-paired windows. unit (c, ln): outputs t0=16*ln..t0+15,
    // window x[t0-6 .. t0+21].
    //   p in [0,14):  xe_p = (pool[t0-6+2p], pool[t0-6+2p+1])
    //   p in [14,27): xo_q = (pool[t0-5+2q], pool[t0-4+2q]), q=p-14
    for (int s = tid; s < XS_ULL; s += 256) {
        int unit = s / 27, p = s - unit * 27;
        int c = unit >> 4, ln = unit & 15;
        int base = c * 272 + ln * 16;
        int idx = (p < 14) ? (base + 2 * p) : (base + 1 + 2 * (p - 14));
        xs[s] = pk2(xpf[idx], xpf[idx + 1]);
    }
    __syncthreads();

    // phase 3: packed weights for this block's 16 o overwrite xpf; BN consts
    for (int i = tid; i < W2A_ULL; i += 256) {
        float wv = cw[og * W2A_ULL + i];
        w2[i] = pk2(wv, wv);
    }
    if (tid < 16) {
        int o = og * 16 + tid;
        float inv = bg[o] * rsqrtf(bv[o] + 1e-5f);
        sc[tid] = inv;
        sh[tid] = cb[o] * inv + bbv[o] - bm[o] * inv;
    }
    __syncthreads();

    // phase 4: compute. thread -> (lo = tid>>4, ln = tid&15), 16 t.
    int lo = tid >> 4, ln = tid & 15;
    int o  = og * 16 + lo;
    int t0 = ln * 16;

    ull acc[8];
    #pragma unroll
    for (int u = 0; u < 8; ++u) acc[u] = 0ull;

    #pragma unroll 2
    for (int c = 0; c < CH; ++c) {
        const ull* xr = xs + (c * 16 + ln) * 27;
        ull xe[14], xo[13];
        #pragma unroll
        for (int p = 0; p < 14; ++p) xe[p] = xr[p];
        #pragma unroll
        for (int p = 0; p < 13; ++p) xo[p] = xr[14 + p];

        const ull* wr = w2 + lo * 286 + c * 13;
        #pragma unroll
        for (int k = 0; k < 13; ++k) {
            ull wv = wr[k];
            int m = k >> 1;
            if ((k & 1) == 0) {
                #pragma unroll
                for (int u = 0; u < 8; ++u) fma2(acc[u], xe[m + u], wv);
            } else {
                #pragma unroll
                for (int u = 0; u < 8; ++u) fma2(acc[u], xo[m + u], wv);
            }
        }
    }

    // epilogue: BN + store
    float scl = sc[lo], shf = sh[lo];
    float* zr = g_z + ((size_t)b * ST + o) * TP + t0;
    #pragma unroll
    for (int u = 0; u < 8; ++u) {
        float lov, hiv; upk2(acc[u], lov, hiv);
        int t = t0 + 2 * u;
        if (t < TP)     zr[2 * u]     = lov * scl + shf;
        if (t + 1 < TP) zr[2 * u + 1] = hiv * scl + shf;
    }
}

// ============================================================
// K2: per b: 3 blocks -> center, P = W*Zc, y += P P^T / tr
//     y = y/3 + 1e-5 * W W^T  -> g_y
// ============================================================
__global__ void __launch_bounds__(256)
k_covmap(const float* __restrict__ W)
{
    __shared__ float zs[64 * 85];
    __shared__ float ps[32 * 85];
    __shared__ float Wsh[32 * 64];
    __shared__ float yacc[1024];
    __shared__ float red[256];
    __shared__ float smean[64];
    __shared__ float s_rtr;

    int b = blockIdx.x, tid = threadIdx.x;
    int ri = tid >> 3, j0 = (tid & 7) * 4;

    for (int i = tid; i < 2048; i += 256) Wsh[i] = W[i];
    for (int i = tid; i < 1024; i += 256) yacc[i] = 0.f;
    __syncthreads();

    const int offs[3] = {0, 84, 167};
    const int lens[3] = {84, 83, 83};

    for (int blk = 0; blk < 3; ++blk) {
        int off = offs[blk], l = lens[blk];
        for (int i = tid; i < 64 * l; i += 256) {
            int c = i / l, t = i - c * l;
            zs[c * 85 + t] = g_z[((size_t)b * 64 + c) * TP + off + t];
        }
        __syncthreads();
        if (tid < 64) {
            float s = 0.f;
            for (int t = 0; t < l; ++t) s += zs[tid * 85 + t];
            smean[tid] = s / (float)l;
        }
        __syncthreads();
        float loc = 0.f;
        for (int i = tid; i < 64 * l; i += 256) {
            int c = i / l, t = i - c * l;
            float v = zs[c * 85 + t] - smean[c];
            zs[c * 85 + t] = v;
            loc += v * v;
        }
        red[tid] = loc; __syncthreads();
        for (int s = 128; s > 0; s >>= 1) {
            if (tid < s) red[tid] += red[tid + s];
            __syncthreads();
        }
        if (tid == 0) s_rtr = 1.f / red[0];
        __syncthreads();

        // P(32 x l) = Wsh(32x64) * zs(64 x l)
        {
            int ty = tid >> 4, tx = tid & 15;
            int o0 = 2 * ty;
            float a0[6] = {0,0,0,0,0,0}, a1[6] = {0,0,0,0,0,0};
            for (int c = 0; c < 64; ++c) {
                float w0 = Wsh[o0 * 64 + c];
                float w1 = Wsh[(o0 + 1) * 64 + c];
                const float* zr = zs + c * 85 + tx;
                #pragma unroll
                for (int j = 0; j < 6; ++j) {
                    int t = tx + 16 * j;
                    if (t < l) {
                        float zv = zr[16 * j];
                        a0[j] += w0 * zv;
                        a1[j] += w1 * zv;
                    }
                }
            }
            #pragma unroll
            for (int j = 0; j < 6; ++j) {
                int t = tx + 16 * j;
                if (t < l) {
                    ps[o0 * 85 + t] = a0[j];
                    ps[(o0 + 1) * 85 + t] = a1[j];
                }
            }
        }
        __syncthreads();

        // yacc += rtr * P P^T  (256 threads x 4 entries)
        {
            float a0 = 0.f, a1 = 0.f, a2 = 0.f, a3 = 0.f;
            const float* pu = ps + ri * 85;
            const float* pv = ps + j0 * 85;
            for (int t = 0; t < l; ++t) {
                float u = pu[t];
                a0 += u * pv[t];
                a1 += u * pv[85 + t];
                a2 += u * pv[170 + t];
                a3 += u * pv[255 + t];
            }
            float rtr = s_rtr;
            yacc[ri * 32 + j0]     += a0 * rtr;
            yacc[ri * 32 + j0 + 1] += a1 * rtr;
            yacc[ri * 32 + j0 + 2] += a2 * rtr;
            yacc[ri * 32 + j0 + 3] += a3 * rtr;
        }
        __syncthreads();
    }

    // y = yacc/3 + 1e-5 * W W^T
    {
        float a0 = 0.f, a1 = 0.f, a2 = 0.f, a3 = 0.f;
        const float* wu = Wsh + ri * 64;
        const float* wv = Wsh + j0 * 64;
        for (int c = 0; c < 64; ++c) {
            float u = wu[c];
            a0 += u * wv[c];
            a1 += u * wv[64 + c];
            a2 += u * wv[128 + c];
            a3 += u * wv[192 + c];
        }
        float* yr = g_y + (size_t)b * 1024 + ri * 32 + j0;
        yr[0] = yacc[ri * 32 + j0]     * (1.f / 3.f) + 1e-5f * a0;
        yr[1] = yacc[ri * 32 + j0 + 1] * (1.f / 3.f) + 1e-5f * a1;
        yr[2] = yacc[ri * 32 + j0 + 2] * (1.f / 3.f) + 1e-5f * a2;
        yr[3] = yacc[ri * 32 + j0 + 3] * (1.f / 3.f) + 1e-5f * a3;
    }
}

// ============================================================
// K3: one warp per 32x32 SPD matrix: Hestenes Jacobi eigh,
//     logm = U log(max(lam,1e-4)) U^T, write scaled triu -> fe
// ============================================================
__global__ void __launch_bounds__(256)
k_eig(float* __restrict__ feout)
{
    __shared__ float sm[8 * 1088];

    int tid = threadIdx.x;
    int wid = tid >> 5, lane = tid & 31;
    int b = blockIdx.x * 8 + wid;
    if (b >= BB) return;

    const float* Y = g_y + (size_t)b * 1024;
    float a[32];
    #pragma unroll
    for (int i = 0; i < 32; ++i) a[i] = Y[i * 32 + lane];

    for (int sweep = 0; sweep < 8; ++sweep) {
        for (int r = 0; r < 31; ++r) {
            int partner;
            if (lane == 0) partner = (30 + r) % 31 + 1;
            else {
                int pos = ((lane - 1 - r) % 31 + 31) % 31 + 1;
                int pp = 31 - pos;
                partner = (pp == 0) ? 0 : ((pp - 1 + r) % 31) + 1;
            }
            float oth[32];
            #pragma unroll
            for (int i = 0; i < 32; ++i)
                oth[i] = __shfl_sync(0xffffffffu, a[i], partner);
            float own = 0.f, dot = 0.f;
            #pragma unroll
            for (int i = 0; i < 32; ++i) { own += a[i] * a[i]; dot += a[i] * oth[i]; }
            float othn = __shfl_sync(0xffffffffu, own, partner);
            bool isp = lane < partner;
            float app = isp ? own : othn;
            float aqq = isp ? othn : own;
            float c = 1.f, s = 0.f;
            if (dot * dot > 1e-24f * app * aqq) {
                float zeta = (aqq - app) / (2.f * dot);
                float t = ((zeta >= 0.f) ? 1.f : -1.f) /
                          (fabsf(zeta) + sqrtf(1.f + zeta * zeta));
                c = rsqrtf(1.f + t * t);
                s = c * t;
            }
            #pragma unroll
            for (int i = 0; i < 32; ++i)
                a[i] = isp ? (c * a[i] - s * oth[i]) : (s * oth[i] + c * a[i]);
        }
    }

    float own = 0.f;
    #pragma unroll
    for (int i = 0; i < 32; ++i) own += a[i] * a[i];
    float lam = sqrtf(own);
    float g = logf(fmaxf(lam, 1e-4f));
    float inv = 1.f / lam;

    float* Us = sm + wid * 1088;
    float* gs = Us + 1056;
    #pragma unroll
    for (int i = 0; i < 32; ++i) Us[lane * 33 + i] = a[i] * inv;
    gs[lane] = g;
    __syncwarp();

    float scal[32];
    #pragma unroll
    for (int j = 0; j < 32; ++j) scal[j] = gs[j] * Us[j * 33 + lane];
    float acc[32];
    #pragma unroll
    for (int i = 0; i < 32; ++i) acc[i] = 0.f;
    #pragma unroll
    for (int j = 0; j < 32; ++j) {
        float sj = scal[j];
        #pragma unroll
        for (int i = 0; i < 32; ++i) acc[i] += sj * Us[j * 33 + i];
    }

    const float SQ2 = 1.41421356237309515f;
    int bi = 32 * lane - (lane * (lane - 1)) / 2 - lane;
    float* fb = feout + (size_t)b * NFE + bi;
    #pragma unroll
    for (int j = 0; j < 32; ++j) {
        if (j >= lane) fb[j] = acc[j] * ((j == lane) ? 1.f : SQ2);
    }
}

// ============================================================
// K4: logits(256,4) = fe(256,4752) @ Wl(4,4752)^T + bl
// ============================================================
__global__ void __launch_bounds__(128)
k_linear(const float* __restrict__ fe, const float* __restrict__ Wl,
         const float* __restrict__ bl, float* __restrict__ out)
{
    __shared__ float red[128 * 4];
    int bs = blockIdx.x, tid = threadIdx.x;
    const float* fr = fe + (size_t)bs * 4752;
    float acc[4] = {0.f, 0.f, 0.f, 0.f};
    for (int i = tid; i < 4752; i += 128) {
        float v = fr[i];
        #pragma unroll
        for (int c = 0; c < 4; ++c) acc[c] += v * Wl[c * 4752 + i];
    }
    #pragma unroll
    for (int c = 0; c < 4; ++c) red[tid * 4 + c] = acc[c];
    __syncthreads();
    for (int s = 64; s > 0; s >>= 1) {
        if (tid < s) {
            #pragma unroll
            for (int c = 0; c < 4; ++c) red[tid * 4 + c] += red[(tid + s) * 4 + c];
        }
        __syncthreads();
    }
    if (tid < 4) out[bs * 4 + tid] = red[tid] + bl[tid];
}

extern "C" void kernel_launch(void* const* d_in, const int* in_sizes, int n_in,
                              void* d_out, int out_size) {
    const float* x   = (const float*)d_in[0];
    const float* cw  = (const float*)d_in[1];
    const float* cb  = (const float*)d_in[2];
    const float* bg  = (const float*)d_in[3];
    const float* bb  = (const float*)d_in[4];
    const float* bm  = (const float*)d_in[5];
    const float* bv  = (const float*)d_in[6];
    const float* W   = (const float*)d_in[7];
    const float* Wl  = (const float*)d_in[8];
    const float* bl  = (const float*)d_in[9];
    float* fe     = (float*)d_out;
    float* logits = fe + (size_t)BB * NFE;

    static int smem_set = 0;
    if (!smem_set) {
        cudaFuncSetAttribute(k_conv, cudaFuncAttributeMaxDynamicSharedMemorySize,
                             CONV_SMEM);
        smem_set = 1;
    }

    k_conv<<<dim3(4, BB), 256, CONV_SMEM>>>(x, cw, cb, bg, bb, bm, bv);
    k_covmap<<<BB, 256>>>(W);
    k_eig<<<BB / 8, 256>>>(fe);
    k_linear<<<256, 128>>>(fe, Wl, bl, logits);
}

// round 7
// speedup vs baseline: 1.2097x; 1.2097x over previous
#include <cuda_runtime.h>
#include <cuda_bf16.h>
#include <math.h>

#define BB    2304
#define CH    22
#define TP    250
#define ST    64
#define KW    13
#define RR    32
#define NFE   528

typedef unsigned long long ull;

__device__ float g_z[(size_t)BB * ST * TP];
__device__ float g_y[(size_t)BB * RR * RR];
__device__ float g_xp[(size_t)BB * CH * 272];   // pooled + padded input
__device__ ull   g_w2[ST * 286];                // (w,w) packed weights

__device__ __forceinline__ ull pk2(float a, float b) {
    ull r;
    asm("mov.b64 %0, {%1, %2};" : "=l"(r)
        : "r"(__float_as_uint(a)), "r"(__float_as_uint(b)));
    return r;
}
__device__ __forceinline__ void upk2(ull v, float &a, float &b) {
    unsigned int lo, hi;
    asm("mov.b64 {%0, %1}, %2;" : "=r"(lo), "=r"(hi) : "l"(v));
    a = __uint_as_float(lo); b = __uint_as_float(hi);
}
__device__ __forceinline__ void fma2(ull &d, ull a, ull b) {
    asm("fma.rn.f32x2 %0, %1, %2, %0;" : "+l"(d) : "l"(a), "l"(b));
}

// ============================================================
// K0a: pool(4) + zero-pad once per b -> g_xp[b][c][272]
//   g_xp[..][tt] = mean4(x[.., tt-6]) for tt in [6,256), else 0
// ============================================================
__global__ void __launch_bounds__(128)
k_prep(const float* __restrict__ x)
{
    int b = blockIdx.x, tid = threadIdx.x;
    const float4* xb = (const float4*)(x + (size_t)b * CH * 1000);
    float* dst = g_xp + (size_t)b * CH * 272;
    for (int i = tid; i < CH * 272; i += 128) {
        int c = i / 272, tt = i - c * 272;
        float v = 0.f;
        if (tt >= 6 && tt < 256) {
            float4 p = xb[c * TP + (tt - 6)];
            v = 0.25f * (p.x + p.y + p.z + p.w);
        }
        dst[i] = v;
    }
}

// K0b: pack conv weights as (w,w) ull pairs
__global__ void __launch_bounds__(256)
k_wpack(const float* __restrict__ cw)
{
    int i = blockIdx.x * 256 + threadIdx.x;
    if (i < ST * 286) {
        float w = cw[i];
        g_w2[i] = pk2(w, w);
    }
}

// ============================================================
// K1: conv(22x13) + BN -> g_z[b][o][t]
// grid (2, BB): og = 32 output channels. 256 threads.
// thread = unit u (and u+256): o2 = u&15 (o-pair), chunk = u>>4 (10 t).
// x window (22 floats) loaded+packed once, reused for both o's.
// smem: xp floats (23.9KB) + w2s 32x287 ull padded (73.5KB) = ~97.5KB
// ============================================================
#define W2S_ULL   (32 * 287)
#define CONV_SMEM (CH * 272 * 4 + W2S_ULL * 8)

__global__ void __launch_bounds__(256, 2)
k_conv(const float* __restrict__ cb, const float* __restrict__ bg,
       const float* __restrict__ bbv, const float* __restrict__ bm,
       const float* __restrict__ bv)
{
    extern __shared__ float dsm[];
    float* xp  = dsm;                          // CH*272 floats
    ull*   w2s = (ull*)(dsm + CH * 272);       // 32 x 287 (padded rows)
    __shared__ float sc[32], sh[32];

    int og = blockIdx.x, b = blockIdx.y, tid = threadIdx.x;

    // load pooled input (float4) and packed weights
    {
        const float4* src = (const float4*)(g_xp + (size_t)b * CH * 272);
        float4* d4 = (float4*)xp;
        for (int i = tid; i < CH * 272 / 4; i += 256) d4[i] = src[i];
        const ull* wsrc = g_w2 + og * 32 * 286;
        for (int i = tid; i < 32 * 286; i += 256) {
            int ol = i / 286, k = i - ol * 286;
            w2s[ol * 287 + k] = wsrc[i];
        }
        if (tid < 32) {
            int o = og * 32 + tid;
            float inv = bg[o] * rsqrtf(bv[o] + 1e-5f);
            sc[tid] = inv;
            sh[tid] = cb[o] * inv + bbv[o] - bm[o] * inv;
        }
    }
    __syncthreads();

    #pragma unroll 1
    for (int u = tid; u < 400; u += 256) {
        int o2 = u & 15, chunk = u >> 4;
        int t0 = chunk * 10;
        int ol0 = 2 * o2;

        ull acc0[5], acc1[5];
        #pragma unroll
        for (int j = 0; j < 5; ++j) { acc0[j] = 0ull; acc1[j] = 0ull; }

        #pragma unroll 2
        for (int c = 0; c < CH; ++c) {
            const float* pb = xp + c * 272 + t0;
            float p[22];
            #pragma unroll
            for (int j = 0; j < 22; ++j) p[j] = pb[j];
            ull xe[11], xo[10];
            #pragma unroll
            for (int j = 0; j < 11; ++j) xe[j] = pk2(p[2 * j], p[2 * j + 1]);
            #pragma unroll
            for (int j = 0; j < 10; ++j) xo[j] = pk2(p[2 * j + 1], p[2 * j + 2]);

            const ull* w0 = w2s + ol0 * 287 + c * 13;
            const ull* w1 = w0 + 287;
            #pragma unroll
            for (int k = 0; k < 13; ++k) {
                ull wa = w0[k], wb = w1[k];
                int m = k >> 1;
                if ((k & 1) == 0) {
                    #pragma unroll
                    for (int j = 0; j < 5; ++j) {
                        fma2(acc0[j], xe[m + j], wa);
                        fma2(acc1[j], xe[m + j], wb);
                    }
                } else {
                    #pragma unroll
                    for (int j = 0; j < 5; ++j) {
                        fma2(acc0[j], xo[m + j], wa);
                        fma2(acc1[j], xo[m + j], wb);
                    }
                }
            }
        }

        // epilogue: BN + store 10 t for each of 2 o's
        #pragma unroll
        for (int oh = 0; oh < 2; ++oh) {
            int ol = ol0 + oh;
            float scl = sc[ol], shf = sh[ol];
            float* zr = g_z + ((size_t)b * ST + og * 32 + ol) * TP + t0;
            ull* ac = oh ? acc1 : acc0;
            #pragma unroll
            for (int j = 0; j < 5; ++j) {
                float lov, hiv; upk2(ac[j], lov, hiv);
                zr[2 * j]     = lov * scl + shf;
                zr[2 * j + 1] = hiv * scl + shf;
            }
        }
    }
}

// ============================================================
// K2: per b: 3 blocks. Fused centering:
//   s1_c, s2_c -> mean m, rtr = 1/Sum(s2 - s1^2/l)
//   q_o = Sum_c W[o,c] m_c ;  P = W*Z - q ;  yacc += rtr * P P^T
//   y = yacc/3 + 1e-5 * W W^T
// ============================================================
__global__ void __launch_bounds__(256)
k_covmap(const float* __restrict__ W)
{
    __shared__ float zs[64 * 85];
    __shared__ float ps[32 * 85];
    __shared__ float Wsh[2048];
    __shared__ float yacc[1024];
    __shared__ float redv[64];
    __shared__ float smean[64];
    __shared__ float qsh[32];
    __shared__ float s_rtr;

    int b = blockIdx.x, tid = threadIdx.x;
    int ri = tid >> 3, j0 = (tid & 7) * 4;

    for (int i = tid; i < 2048; i += 256) Wsh[i] = W[i];
    for (int i = tid; i < 1024; i += 256) yacc[i] = 0.f;
    __syncthreads();

    const int offs[3] = {0, 84, 167};
    const int lens[3] = {84, 83, 83};

    for (int blk = 0; blk < 3; ++blk) {
        int off = offs[blk], l = lens[blk];
        float flin = 1.f / (float)l;

        for (int i = tid; i < 64 * l; i += 256) {
            int c = i / l, t = i - c * l;
            zs[c * 85 + t] = g_z[((size_t)b * 64 + c) * TP + off + t];
        }
        __syncthreads();

        // s1/s2 per channel: 4 threads per c
        {
            int c = tid >> 2, qq = tid & 3;
            float s1 = 0.f, s2 = 0.f;
            for (int t = qq; t < l; t += 4) {
                float v = zs[c * 85 + t];
                s1 += v; s2 += v * v;
            }
            s1 += __shfl_xor_sync(0xffffffffu, s1, 1);
            s2 += __shfl_xor_sync(0xffffffffu, s2, 1);
            s1 += __shfl_xor_sync(0xffffffffu, s1, 2);
            s2 += __shfl_xor_sync(0xffffffffu, s2, 2);
            if (qq == 0) {
                smean[c] = s1 * flin;
                redv[c]  = s2 - s1 * s1 * flin;
            }
        }
        __syncthreads();

        if (tid < 32) {
            float v = redv[tid] + redv[tid + 32];
            v += __shfl_xor_sync(0xffffffffu, v, 16);
            v += __shfl_xor_sync(0xffffffffu, v, 8);
            v += __shfl_xor_sync(0xffffffffu, v, 4);
            v += __shfl_xor_sync(0xffffffffu, v, 2);
            v += __shfl_xor_sync(0xffffffffu, v, 1);
            if (tid == 0) s_rtr = 1.f / v;
        }
        // q_o = Sum_c W[o,c] * m_c  (8 threads per o)
        {
            int o = tid >> 3, sub = tid & 7;
            float qv = 0.f;
            for (int c = sub; c < 64; c += 8)
                qv += Wsh[o * 64 + c] * smean[c];
            qv += __shfl_xor_sync(0xffffffffu, qv, 1);
            qv += __shfl_xor_sync(0xffffffffu, qv, 2);
            qv += __shfl_xor_sync(0xffffffffu, qv, 4);
            if (sub == 0) qsh[o] = qv;
        }
        __syncthreads();

        // P(32 x l) = Wsh * Z - q
        {
            int ty = tid >> 4, tx = tid & 15;
            int o0 = 2 * ty;
            float a0[6] = {0,0,0,0,0,0}, a1[6] = {0,0,0,0,0,0};
            for (int c = 0; c < 64; ++c) {
                float w0 = Wsh[o0 * 64 + c];
                float w1 = Wsh[(o0 + 1) * 64 + c];
                const float* zr = zs + c * 85 + tx;
                #pragma unroll
                for (int j = 0; j < 6; ++j) {
                    int t = tx + 16 * j;
                    if (t < l) {
                        float zv = zr[16 * j];
                        a0[j] += w0 * zv;
                        a1[j] += w1 * zv;
                    }
                }
            }
            float q0 = qsh[o0], q1 = qsh[o0 + 1];
            #pragma unroll
            for (int j = 0; j < 6; ++j) {
                int t = tx + 16 * j;
                if (t < l) {
                    ps[o0 * 85 + t] = a0[j] - q0;
                    ps[(o0 + 1) * 85 + t] = a1[j] - q1;
                }
            }
        }
        __syncthreads();

        // yacc += rtr * P P^T
        {
            float a0 = 0.f, a1 = 0.f, a2 = 0.f, a3 = 0.f;
            const float* pu = ps + ri * 85;
            const float* pv = ps + j0 * 85;
            for (int t = 0; t < l; ++t) {
                float u = pu[t];
                a0 += u * pv[t];
                a1 += u * pv[85 + t];
                a2 += u * pv[170 + t];
                a3 += u * pv[255 + t];
            }
            float rtr = s_rtr;
            yacc[ri * 32 + j0]     += a0 * rtr;
            yacc[ri * 32 + j0 + 1] += a1 * rtr;
            yacc[ri * 32 + j0 + 2] += a2 * rtr;
            yacc[ri * 32 + j0 + 3] += a3 * rtr;
        }
        __syncthreads();
    }

    // y = yacc/3 + 1e-5 * W W^T
    {
        float a0 = 0.f, a1 = 0.f, a2 = 0.f, a3 = 0.f;
        const float* wu = Wsh + ri * 64;
        const float* wv = Wsh + j0 * 64;
        for (int c = 0; c < 64; ++c) {
            float u = wu[c];
            a0 += u * wv[c];
            a1 += u * wv[64 + c];
            a2 += u * wv[128 + c];
            a3 += u * wv[192 + c];
        }
        float* yr = g_y + (size_t)b * 1024 + ri * 32 + j0;
        yr[0] = yacc[ri * 32 + j0]     * (1.f / 3.f) + 1e-5f * a0;
        yr[1] = yacc[ri * 32 + j0 + 1] * (1.f / 3.f) + 1e-5f * a1;
        yr[2] = yacc[ri * 32 + j0 + 2] * (1.f / 3.f) + 1e-5f * a2;
        yr[3] = yacc[ri * 32 + j0 + 3] * (1.f / 3.f) + 1e-5f * a3;
    }
}

// ============================================================
// K3: one warp per 32x32 SPD: Hestenes Jacobi (6 sweeps),
//     logm = U log(max(lam,1e-4)) U^T, scaled triu -> fe
// ============================================================
__global__ void __launch_bounds__(256)
k_eig(float* __restrict__ feout)
{
    __shared__ float sm[8 * 1088];

    int tid = threadIdx.x;
    int wid = tid >> 5, lane = tid & 31;
    int b = blockIdx.x * 8 + wid;
    if (b >= BB) return;

    const float* Y = g_y + (size_t)b * 1024;
    float a[32];
    #pragma unroll
    for (int i = 0; i < 32; ++i) a[i] = Y[i * 32 + lane];

    for (int sweep = 0; sweep < 6; ++sweep) {
        for (int r = 0; r < 31; ++r) {
            int partner;
            if (lane == 0) partner = (30 + r) % 31 + 1;
            else {
                int pos = ((lane - 1 - r) % 31 + 31) % 31 + 1;
                int pp = 31 - pos;
                partner = (pp == 0) ? 0 : ((pp - 1 + r) % 31) + 1;
            }
            float oth[32];
            #pragma unroll
            for (int i = 0; i < 32; ++i)
                oth[i] = __shfl_sync(0xffffffffu, a[i], partner);
            float own = 0.f, dot = 0.f;
            #pragma unroll
            for (int i = 0; i < 32; ++i) { own += a[i] * a[i]; dot += a[i] * oth[i]; }
            float othn = __shfl_sync(0xffffffffu, own, partner);
            bool isp = lane < partner;
            float app = isp ? own : othn;
            float aqq = isp ? othn : own;
            float c = 1.f, s = 0.f;
            if (dot * dot > 1e-24f * app * aqq) {
                float zeta = (aqq - app) / (2.f * dot);
                float t = ((zeta >= 0.f) ? 1.f : -1.f) /
                          (fabsf(zeta) + sqrtf(1.f + zeta * zeta));
                c = rsqrtf(1.f + t * t);
                s = c * t;
            }
            #pragma unroll
            for (int i = 0; i < 32; ++i)
                a[i] = isp ? (c * a[i] - s * oth[i]) : (s * oth[i] + c * a[i]);
        }
    }

    float own = 0.f;
    #pragma unroll
    for (int i = 0; i < 32; ++i) own += a[i] * a[i];
    float lam = sqrtf(own);
    float g = logf(fmaxf(lam, 1e-4f));
    float inv = 1.f / lam;

    float* Us = sm + wid * 1088;
    float* gs = Us + 1056;
    #pragma unroll
    for (int i = 0; i < 32; ++i) Us[lane * 33 + i] = a[i] * inv;
    gs[lane] = g;
    __syncwarp();

    float scal[32];
    #pragma unroll
    for (int j = 0; j < 32; ++j) scal[j] = gs[j] * Us[j * 33 + lane];
    float acc[32];
    #pragma unroll
    for (int i = 0; i < 32; ++i) acc[i] = 0.f;
    #pragma unroll
    for (int j = 0; j < 32; ++j) {
        float sj = scal[j];
        #pragma unroll
        for (int i = 0; i < 32; ++i) acc[i] += sj * Us[j * 33 + i];
    }

    const float SQ2 = 1.41421356237309515f;
    int bi = 32 * lane - (lane * (lane - 1)) / 2 - lane;
    float* fb = feout + (size_t)b * NFE + bi;
    #pragma unroll
    for (int j = 0; j < 32; ++j) {
        if (j >= lane) fb[j] = acc[j] * ((j == lane) ? 1.f : SQ2);
    }
}

// ============================================================
// K4: logits(256,4) = fe(256,4752) @ Wl(4,4752)^T + bl
// ============================================================
__global__ void __launch_bounds__(128)
k_linear(const float* __restrict__ fe, const float* __restrict__ Wl,
         const float* __restrict__ bl, float* __restrict__ out)
{
    __shared__ float red[128 * 4];
    int bs = blockIdx.x, tid = threadIdx.x;
    const float* fr = fe + (size_t)bs * 4752;
    float acc[4] = {0.f, 0.f, 0.f, 0.f};
    for (int i = tid; i < 4752; i += 128) {
        float v = fr[i];
        #pragma unroll
        for (int c = 0; c < 4; ++c) acc[c] += v * Wl[c * 4752 + i];
    }
    #pragma unroll
    for (int c = 0; c < 4; ++c) red[tid * 4 + c] = acc[c];
    __syncthreads();
    for (int s = 64; s > 0; s >>= 1) {
        if (tid < s) {
            #pragma unroll
            for (int c = 0; c < 4; ++c) red[tid * 4 + c] += red[(tid + s) * 4 + c];
        }
        __syncthreads();
    }
    if (tid < 4) out[bs * 4 + tid] = red[tid] + bl[tid];
}

extern "C" void kernel_launch(void* const* d_in, const int* in_sizes, int n_in,
                              void* d_out, int out_size) {
    const float* x   = (const float*)d_in[0];
    const float* cw  = (const float*)d_in[1];
    const float* cb  = (const float*)d_in[2];
    const float* bg  = (const float*)d_in[3];
    const float* bb  = (const float*)d_in[4];
    const float* bm  = (const float*)d_in[5];
    const float* bv  = (const float*)d_in[6];
    const float* W   = (const float*)d_in[7];
    const float* Wl  = (const float*)d_in[8];
    const float* bl  = (const float*)d_in[9];
    float* fe     = (float*)d_out;
    float* logits = fe + (size_t)BB * NFE;

    static int smem_set = 0;
    if (!smem_set) {
        cudaFuncSetAttribute(k_conv, cudaFuncAttributeMaxDynamicSharedMemorySize,
                             CONV_SMEM);
        smem_set = 1;
    }

    k_wpack<<<(ST * 286 + 255) / 256, 256>>>(cw);
    k_prep<<<BB, 128>>>(x);
    k_conv<<<dim3(2, BB), 256, CONV_SMEM>>>(cb, bg, bb, bm, bv);
    k_covmap<<<BB, 256>>>(W);
    k_eig<<<BB / 8, 256>>>(fe);
    k_linear<<<256, 128>>>(fe, Wl, bl, logits);
}

// round 8
// speedup vs baseline: 1.3078x; 1.0810x over previous
#include <cuda_runtime.h>
#include <cuda_bf16.h>
#include <math.h>

#define BB    2304
#define CH    22
#define TP    250
#define ST    64
#define KW    13
#define RR    32
#define NFE   528

typedef unsigned long long ull;

__device__ float g_z[(size_t)BB * ST * TP];
__device__ float g_y[(size_t)BB * RR * RR];
__device__ float g_xp[(size_t)BB * CH * 272];   // pooled + padded input
__device__ ull   g_w2[ST * 286];                // (w,w) packed weights

__device__ __forceinline__ ull pk2(float a, float b) {
    ull r;
    asm("mov.b64 %0, {%1, %2};" : "=l"(r)
        : "r"(__float_as_uint(a)), "r"(__float_as_uint(b)));
    return r;
}
__device__ __forceinline__ void upk2(ull v, float &a, float &b) {
    unsigned int lo, hi;
    asm("mov.b64 {%0, %1}, %2;" : "=r"(lo), "=r"(hi) : "l"(v));
    a = __uint_as_float(lo); b = __uint_as_float(hi);
}
__device__ __forceinline__ void fma2(ull &d, ull a, ull b) {
    asm("fma.rn.f32x2 %0, %1, %2, %0;" : "+l"(d) : "l"(a), "l"(b));
}

// ============================================================
// K0a: pool(4) + zero-pad once per b -> g_xp[b][c][272]
// ============================================================
__global__ void __launch_bounds__(128)
k_prep(const float* __restrict__ x)
{
    int b = blockIdx.x, tid = threadIdx.x;
    const float4* xb = (const float4*)(x + (size_t)b * CH * 1000);
    float* dst = g_xp + (size_t)b * CH * 272;
    for (int i = tid; i < CH * 272; i += 128) {
        int c = i / 272, tt = i - c * 272;
        float v = 0.f;
        if (tt >= 6 && tt < 256) {
            float4 p = xb[c * TP + (tt - 6)];
            v = 0.25f * (p.x + p.y + p.z + p.w);
        }
        dst[i] = v;
    }
}

// K0b: pack conv weights as (w,w) ull pairs
__global__ void __launch_bounds__(256)
k_wpack(const float* __restrict__ cw)
{
    int i = blockIdx.x * 256 + threadIdx.x;
    if (i < ST * 286) {
        float w = cw[i];
        g_w2[i] = pk2(w, w);
    }
}

// ============================================================
// K1: conv(22x13) + BN -> g_z[b][o][t]   (unchanged from R7)
// ============================================================
#define W2S_ULL   (32 * 287)
#define CONV_SMEM (CH * 272 * 4 + W2S_ULL * 8)

__global__ void __launch_bounds__(256, 2)
k_conv(const float* __restrict__ cb, const float* __restrict__ bg,
       const float* __restrict__ bbv, const float* __restrict__ bm,
       const float* __restrict__ bv)
{
    extern __shared__ float dsm[];
    float* xp  = dsm;
    ull*   w2s = (ull*)(dsm + CH * 272);
    __shared__ float sc[32], sh[32];

    int og = blockIdx.x, b = blockIdx.y, tid = threadIdx.x;

    {
        const float4* src = (const float4*)(g_xp + (size_t)b * CH * 272);
        float4* d4 = (float4*)xp;
        for (int i = tid; i < CH * 272 / 4; i += 256) d4[i] = src[i];
        const ull* wsrc = g_w2 + og * 32 * 286;
        for (int i = tid; i < 32 * 286; i += 256) {
            int ol = i / 286, k = i - ol * 286;
            w2s[ol * 287 + k] = wsrc[i];
        }
        if (tid < 32) {
            int o = og * 32 + tid;
            float inv = bg[o] * rsqrtf(bv[o] + 1e-5f);
            sc[tid] = inv;
            sh[tid] = cb[o] * inv + bbv[o] - bm[o] * inv;
        }
    }
    __syncthreads();

    #pragma unroll 1
    for (int u = tid; u < 400; u += 256) {
        int o2 = u & 15, chunk = u >> 4;
        int t0 = chunk * 10;
        int ol0 = 2 * o2;

        ull acc0[5], acc1[5];
        #pragma unroll
        for (int j = 0; j < 5; ++j) { acc0[j] = 0ull; acc1[j] = 0ull; }

        #pragma unroll 2
        for (int c = 0; c < CH; ++c) {
            const float* pb = xp + c * 272 + t0;
            float p[22];
            #pragma unroll
            for (int j = 0; j < 22; ++j) p[j] = pb[j];
            ull xe[11], xo[10];
            #pragma unroll
            for (int j = 0; j < 11; ++j) xe[j] = pk2(p[2 * j], p[2 * j + 1]);
            #pragma unroll
            for (int j = 0; j < 10; ++j) xo[j] = pk2(p[2 * j + 1], p[2 * j + 2]);

            const ull* w0 = w2s + ol0 * 287 + c * 13;
            const ull* w1 = w0 + 287;
            #pragma unroll
            for (int k = 0; k < 13; ++k) {
                ull wa = w0[k], wb = w1[k];
                int m = k >> 1;
                if ((k & 1) == 0) {
                    #pragma unroll
                    for (int j = 0; j < 5; ++j) {
                        fma2(acc0[j], xe[m + j], wa);
                        fma2(acc1[j], xe[m + j], wb);
                    }
                } else {
                    #pragma unroll
                    for (int j = 0; j < 5; ++j) {
                        fma2(acc0[j], xo[m + j], wa);
                        fma2(acc1[j], xo[m + j], wb);
                    }
                }
            }
        }

        #pragma unroll
        for (int oh = 0; oh < 2; ++oh) {
            int ol = ol0 + oh;
            float scl = sc[ol], shf = sh[ol];
            float* zr = g_z + ((size_t)b * ST + og * 32 + ol) * TP + t0;
            ull* ac = oh ? acc1 : acc0;
            #pragma unroll
            for (int j = 0; j < 5; ++j) {
                float lov, hiv; upk2(ac[j], lov, hiv);
                zr[2 * j]     = lov * scl + shf;
                zr[2 * j + 1] = hiv * scl + shf;
            }
        }
    }
}

// ============================================================
// K2: covmap rewrite.
//   A = Sum_blk rtr*(Z Z^T - s1 s1^T / l),  rtr = 1/Sum_c(s2 - s1^2/l)
//   y = (1/3) W A W^T + 1e-5 W W^T
// ZZ^T: 4x4 register tiles (interleaved rows, stride 16),
// ulonglong2 LDS.128 + FFMA2, accumulators live in regs across blocks.
// zs pitch 92 floats (23 x 16B, odd mod 8 -> <=2-way conflicts).
// ============================================================
__global__ void __launch_bounds__(256, 2)
k_covmap(const float* __restrict__ W)
{
    __shared__ __align__(16) float zs[64 * 92];     // aliased as A (64 x 68) later
    __shared__ __align__(16) float Wsh[32 * 64];
    __shared__ __align__(16) float Bsh[32 * 72];
    __shared__ float s1sh[64];
    __shared__ float redv[64];
    __shared__ float s_rtr;

    int b = blockIdx.x, tid = threadIdx.x;
    int ti = tid >> 4, tj = tid & 15;

    for (int i = tid; i < 2048; i += 256) Wsh[i] = W[i];

    const int offs[3] = {0, 84, 167};
    const int lens[3] = {84, 83, 83};

    float acc[4][4];
    #pragma unroll
    for (int a = 0; a < 4; ++a)
        #pragma unroll
        for (int e = 0; e < 4; ++e) acc[a][e] = 0.f;

    for (int blk = 0; blk < 3; ++blk) {
        int off = offs[blk], l = lens[blk];
        float flin = 1.f / (float)l;
        __syncthreads();
        // load Z rows, zero-pad to 92
        for (int i = tid; i < 64 * 92; i += 256) {
            int c = i / 92, t = i - c * 92;
            zs[i] = (t < l) ? g_z[((size_t)b * 64 + c) * TP + off + t] : 0.f;
        }
        __syncthreads();
        // s1/s2 per channel: c = tid>>2, q = tid&3 (float4 over 23 units)
        {
            int c = tid >> 2, q = tid & 3;
            const float4* zr = (const float4*)(zs + c * 92);
            float s1 = 0.f, s2 = 0.f;
            for (int t4 = q; t4 < 23; t4 += 4) {
                float4 v = zr[t4];
                s1 += v.x + v.y + v.z + v.w;
                s2 += v.x * v.x + v.y * v.y + v.z * v.z + v.w * v.w;
            }
            s1 += __shfl_xor_sync(0xffffffffu, s1, 1);
            s2 += __shfl_xor_sync(0xffffffffu, s2, 1);
            s1 += __shfl_xor_sync(0xffffffffu, s1, 2);
            s2 += __shfl_xor_sync(0xffffffffu, s2, 2);
            if (q == 0) { s1sh[c] = s1; redv[c] = s2 - s1 * s1 * flin; }
        }
        __syncthreads();
        if (tid < 32) {
            float v = redv[tid] + redv[tid + 32];
            v += __shfl_xor_sync(0xffffffffu, v, 16);
            v += __shfl_xor_sync(0xffffffffu, v, 8);
            v += __shfl_xor_sync(0xffffffffu, v, 4);
            v += __shfl_xor_sync(0xffffffffu, v, 2);
            v += __shfl_xor_sync(0xffffffffu, v, 1);
            if (tid == 0) s_rtr = 1.f / v;
        }
        __syncthreads();

        // ZZ^T tile: rows i = ti+16a, cols j = tj+16e
        ull zz2[4][4];
        #pragma unroll
        for (int a = 0; a < 4; ++a)
            #pragma unroll
            for (int e = 0; e < 4; ++e) zz2[a][e] = 0ull;

        const ulonglong2* Z2 = (const ulonglong2*)zs;
        #pragma unroll 1
        for (int t4 = 0; t4 < 23; ++t4) {
            ulonglong2 uu[4], vv[4];
            #pragma unroll
            for (int a = 0; a < 4; ++a) uu[a] = Z2[(ti + 16 * a) * 23 + t4];
            #pragma unroll
            for (int e = 0; e < 4; ++e) vv[e] = Z2[(tj + 16 * e) * 23 + t4];
            #pragma unroll
            for (int a = 0; a < 4; ++a)
                #pragma unroll
                for (int e = 0; e < 4; ++e) {
                    fma2(zz2[a][e], uu[a].x, vv[e].x);
                    fma2(zz2[a][e], uu[a].y, vv[e].y);
                }
        }
        float rtr = s_rtr;
        #pragma unroll
        for (int a = 0; a < 4; ++a) {
            float s1i = s1sh[ti + 16 * a] * flin * rtr;
            #pragma unroll
            for (int e = 0; e < 4; ++e) {
                float lo, hi; upk2(zz2[a][e], lo, hi);
                acc[a][e] += rtr * (lo + hi) - s1i * s1sh[tj + 16 * e];
            }
        }
    }
    __syncthreads();
    // store A into zs alias, pitch 68
    {
        float* A = zs;
        #pragma unroll
        for (int a = 0; a < 4; ++a)
            #pragma unroll
            for (int e = 0; e < 4; ++e)
                A[(ti + 16 * a) * 68 + tj + 16 * e] = acc[a][e];
    }
    __syncthreads();
    // B = W * A  (32 x 64): units (o, c4), A pitch 17 units, B pitch 18 units
    {
        const ulonglong2* A2 = (const ulonglong2*)zs;
        ulonglong2* B2 = (ulonglong2*)Bsh;
        #pragma unroll
        for (int pass = 0; pass < 2; ++pass) {
            int u0 = tid + pass * 256;
            int o = u0 >> 4, c4 = u0 & 15;
            ull a2a = 0ull, a2b = 0ull;
            const float* wrow = Wsh + o * 64;
            #pragma unroll 4
            for (int k = 0; k < 64; ++k) {
                float w = wrow[k];
                ull w2 = pk2(w, w);
                ulonglong2 av = A2[k * 17 + c4];
                fma2(a2a, av.x, w2);
                fma2(a2b, av.y, w2);
            }
            ulonglong2 st; st.x = a2a; st.y = a2b;
            B2[o * 18 + c4] = st;
        }
    }
    __syncthreads();
    // y = (1/3) B W^T + 1e-5 W W^T : 64 threads, 4x4 tiles
    if (tid < 64) {
        int o0 = (tid >> 3) * 4, p0 = (tid & 7) * 4;
        ull y2[4][4], wa2[4][4];
        #pragma unroll
        for (int a = 0; a < 4; ++a)
            #pragma unroll
            for (int e = 0; e < 4; ++e) { y2[a][e] = 0ull; wa2[a][e] = 0ull; }

        const ulonglong2* B2 = (const ulonglong2*)Bsh;
        const ulonglong2* W2 = (const ulonglong2*)Wsh;
        #pragma unroll 2
        for (int c4 = 0; c4 < 16; ++c4) {
            ulonglong2 bo[4], wo[4], wp[4];
            #pragma unroll
            for (int a = 0; a < 4; ++a) {
                bo[a] = B2[(o0 + a) * 18 + c4];
                wo[a] = W2[(o0 + a) * 16 + c4];
            }
            #pragma unroll
            for (int e = 0; e < 4; ++e) wp[e] = W2[(p0 + e) * 16 + c4];
            #pragma unroll
            for (int a = 0; a < 4; ++a)
                #pragma unroll
                for (int e = 0; e < 4; ++e) {
                    fma2(y2[a][e], bo[a].x, wp[e].x);
                    fma2(y2[a][e], bo[a].y, wp[e].y);
                    fma2(wa2[a][e], wo[a].x, wp[e].x);
                    fma2(wa2[a][e], wo[a].y, wp[e].y);
                }
        }
        #pragma unroll
        for (int a = 0; a < 4; ++a) {
            float4 ov;
            float lo, hi, wl, wh;
            upk2(y2[a][0], lo, hi); upk2(wa2[a][0], wl, wh);
            ov.x = (lo + hi) * (1.f / 3.f) + 1e-5f * (wl + wh);
            upk2(y2[a][1], lo, hi); upk2(wa2[a][1], wl, wh);
            ov.y = (lo + hi) * (1.f / 3.f) + 1e-5f * (wl + wh);
            upk2(y2[a][2], lo, hi); upk2(wa2[a][2], wl, wh);
            ov.z = (lo + hi) * (1.f / 3.f) + 1e-5f * (wl + wh);
            upk2(y2[a][3], lo, hi); upk2(wa2[a][3], wl, wh);
            ov.w = (lo + hi) * (1.f / 3.f) + 1e-5f * (wl + wh);
            *(float4*)(g_y + (size_t)b * 1024 + (o0 + a) * 32 + p0) = ov;
        }
    }
}

// ============================================================
// K3: one warp per 32x32 SPD: Hestenes Jacobi (6 sweeps),
//     logm = U log(max(lam,1e-4)) U^T, scaled triu -> fe
// ============================================================
__global__ void __launch_bounds__(256)
k_eig(float* __restrict__ feout)
{
    __shared__ float sm[8 * 1088];

    int tid = threadIdx.x;
    int wid = tid >> 5, lane = tid & 31;
    int b = blockIdx.x * 8 + wid;
    if (b >= BB) return;

    const float* Y = g_y + (size_t)b * 1024;
    float a[32];
    #pragma unroll
    for (int i = 0; i < 32; ++i) a[i] = Y[i * 32 + lane];

    for (int sweep = 0; sweep < 6; ++sweep) {
        for (int r = 0; r < 31; ++r) {
            int partner;
            if (lane == 0) partner = (30 + r) % 31 + 1;
            else {
                int pos = ((lane - 1 - r) % 31 + 31) % 31 + 1;
                int pp = 31 - pos;
                partner = (pp == 0) ? 0 : ((pp - 1 + r) % 31) + 1;
            }
            float oth[32];
            #pragma unroll
            for (int i = 0; i < 32; ++i)
                oth[i] = __shfl_sync(0xffffffffu, a[i], partner);
            float own = 0.f, dot = 0.f;
            #pragma unroll
            for (int i = 0; i < 32; ++i) { own += a[i] * a[i]; dot += a[i] * oth[i]; }
            float othn = __shfl_sync(0xffffffffu, own, partner);
            bool isp = lane < partner;
            float app = isp ? own : othn;
            float aqq = isp ? othn : own;
            float c = 1.f, s = 0.f;
            if (dot * dot > 1e-24f * app * aqq) {
                float zeta = (aqq - app) / (2.f * dot);
                float t = ((zeta >= 0.f) ? 1.f : -1.f) /
                          (fabsf(zeta) + sqrtf(1.f + zeta * zeta));
                c = rsqrtf(1.f + t * t);
                s = c * t;
            }
            #pragma unroll
            for (int i = 0; i < 32; ++i)
                a[i] = isp ? (c * a[i] - s * oth[i]) : (s * oth[i] + c * a[i]);
        }
    }

    float own = 0.f;
    #pragma unroll
    for (int i = 0; i < 32; ++i) own += a[i] * a[i];
    float lam = sqrtf(own);
    float g = logf(fmaxf(lam, 1e-4f));
    float inv = 1.f / lam;

    float* Us = sm + wid * 1088;
    float* gs = Us + 1056;
    #pragma unroll
    for (int i = 0; i < 32; ++i) Us[lane * 33 + i] = a[i] * inv;
    gs[lane] = g;
    __syncwarp();

    float scal[32];
    #pragma unroll
    for (int j = 0; j < 32; ++j) scal[j] = gs[j] * Us[j * 33 + lane];
    float acc[32];
    #pragma unroll
    for (int i = 0; i < 32; ++i) acc[i] = 0.f;
    #pragma unroll
    for (int j = 0; j < 32; ++j) {
        float sj = scal[j];
        #pragma unroll
        for (int i = 0; i < 32; ++i) acc[i] += sj * Us[j * 33 + i];
    }

    const float SQ2 = 1.41421356237309515f;
    int bi = 32 * lane - (lane * (lane - 1)) / 2 - lane;
    float* fb = feout + (size_t)b * NFE + bi;
    #pragma unroll
    for (int j = 0; j < 32; ++j) {
        if (j >= lane) fb[j] = acc[j] * ((j == lane) ? 1.f : SQ2);
    }
}

// ============================================================
// K4: logits(256,4) = fe(256,4752) @ Wl(4,4752)^T + bl
// ============================================================
__global__ void __launch_bounds__(128)
k_linear(const float* __restrict__ fe, const float* __restrict__ Wl,
         const float* __restrict__ bl, float* __restrict__ out)
{
    __shared__ float red[128 * 4];
    int bs = blockIdx.x, tid = threadIdx.x;
    const float* fr = fe + (size_t)bs * 4752;
    float acc[4] = {0.f, 0.f, 0.f, 0.f};
    for (int i = tid; i < 4752; i += 128) {
        float v = fr[i];
        #pragma unroll
        for (int c = 0; c < 4; ++c) acc[c] += v * Wl[c * 4752 + i];
    }
    #pragma unroll
    for (int c = 0; c < 4; ++c) red[tid * 4 + c] = acc[c];
    __syncthreads();
    for (int s = 64; s > 0; s >>= 1) {
        if (tid < s) {
            #pragma unroll
            for (int c = 0; c < 4; ++c) red[tid * 4 + c] += red[(tid + s) * 4 + c];
        }
        __syncthreads();
    }
    if (tid < 4) out[bs * 4 + tid] = red[tid] + bl[tid];
}

extern "C" void kernel_launch(void* const* d_in, const int* in_sizes, int n_in,
                              void* d_out, int out_size) {
    const float* x   = (const float*)d_in[0];
    const float* cw  = (const float*)d_in[1];
    const float* cb  = (const float*)d_in[2];
    const float* bg  = (const float*)d_in[3];
    const float* bb  = (const float*)d_in[4];
    const float* bm  = (const float*)d_in[5];
    const float* bv  = (const float*)d_in[6];
    const float* W   = (const float*)d_in[7];
    const float* Wl  = (const float*)d_in[8];
    const float* bl  = (const float*)d_in[9];
    float* fe     = (float*)d_out;
    float* logits = fe + (size_t)BB * NFE;

    static int smem_set = 0;
    if (!smem_set) {
        cudaFuncSetAttribute(k_conv, cudaFuncAttributeMaxDynamicSharedMemorySize,
                             CONV_SMEM);
        smem_set = 1;
    }

    k_wpack<<<(ST * 286 + 255) / 256, 256>>>(cw);
    k_prep<<<BB, 128>>>(x);
    k_conv<<<dim3(2, BB), 256, CONV_SMEM>>>(cb, bg, bb, bm, bv);
    k_covmap<<<BB, 256>>>(W);
    k_eig<<<BB / 8, 256>>>(fe);
    k_linear<<<256, 128>>>(fe, Wl, bl, logits);
}